// round 2
// baseline (speedup 1.0000x reference)
#include <cuda_runtime.h>

// VectorQuantizer: latents [32,64,64,64] (B,D,H,W) fp32, emb_weight [512,64] fp32.
// Output: q_st transposed back to [B,D,H,W] (8388608 floats) followed by vq_loss (1 float).
//
// Numerical contract: reproduce the reference's distance formula
//   dist = fl( fl(Sx + Se_k) - 2*dot_k )   (Sx ~ 64 dominates -> dist quantized at ulp(64))
// with first-index argmin tie-breaking (strict '<' scanning k ascending).
// Sx uses rounded squares summed sequentially (matches naive sum of flat*flat).

#define DD        64
#define KC        512
#define HWPIX     4096          // 64*64
#define TENSOR_ELEMS 8388608    // 32*64*64*64
#define NBLOCKS   512           // 131072 pixels / 256 threads

typedef unsigned long long u64v;

__device__ __forceinline__ u64v fma2(u64v a, u64v b, u64v c) {
    u64v d_;
    asm("fma.rn.f32x2 %0, %1, %2, %3;" : "=l"(d_) : "l"(a), "l"(b), "l"(c));
    return d_;
}
__device__ __forceinline__ u64v add2(u64v a, u64v b) {
    u64v d_;
    asm("add.rn.f32x2 %0, %1, %2;" : "=l"(d_) : "l"(a), "l"(b));
    return d_;
}
__device__ __forceinline__ u64v pack2(float lo, float hi) {
    u64v d_;
    asm("mov.b64 %0, {%1, %2};" : "=l"(d_) : "f"(lo), "f"(hi));
    return d_;
}
__device__ __forceinline__ void unpack2(u64v v, float& lo, float& hi) {
    asm("mov.b64 {%0, %1}, %2;" : "=f"(lo), "=f"(hi) : "l"(v));
}

__device__ float g_partials[NBLOCKS];

__global__ void __launch_bounds__(256, 1)
vq_kernel(const float* __restrict__ lat, const float* __restrict__ emb,
          float* __restrict__ out) {
    extern __shared__ float smem[];
    float* cb  = smem;              // [512][64] codebook
    float* se  = smem + KC * DD;    // [512] sum of squares per code
    float* red = se + KC;           // [8] block reduction scratch

    const int tid = threadIdx.x;

    // Stage codebook in shared (coalesced float4).
    {
        float4* cb4 = (float4*)cb;
        const float4* e4 = (const float4*)emb;
#pragma unroll
        for (int i = 0; i < 32; i++) cb4[tid + 256 * i] = e4[tid + 256 * i];
    }
    __syncthreads();

    // Per-code squared norms: rounded squares, sequential sum.
    for (int k = tid; k < KC; k += 256) {
        const float* r = cb + k * DD;
        float s = 0.f;
#pragma unroll
        for (int d = 0; d < DD; d++) { float t = r[d] * r[d]; s = s + t; }
        se[k] = s;
    }
    __syncthreads();

    // Load this thread's pixel vector x[64] (coalesced per-channel planes),
    // packed as 32 f32x2 values. Sx = sequential sum of rounded squares.
    const int p    = blockIdx.x * 256 + tid;
    const int b    = p >> 12;
    const int base = (b << 18) + (p & (HWPIX - 1));

    u64v xp[32];
    float Sx = 0.f;
#pragma unroll
    for (int i = 0; i < 32; i++) {
        float a = lat[base + ((2 * i) << 12)];
        float c = lat[base + ((2 * i + 1) << 12)];
        float ta = a * a;
        float tc = c * c;
        Sx = Sx + ta;
        Sx = Sx + tc;
        xp[i] = pack2(a, c);
    }

    // Argmin over 512 codes. FFMA2 dot via 4 independent chains.
    float best = 3.4e38f;
    int   bi   = 0;
#pragma unroll 2
    for (int k = 0; k < KC; k++) {
        const ulonglong2* row = (const ulonglong2*)(cb + (k << 6));
        u64v a0 = 0ull, a1 = 0ull, a2 = 0ull, a3 = 0ull;
#pragma unroll
        for (int j = 0; j < 8; j++) {
            ulonglong2 ea = row[2 * j];
            ulonglong2 eb = row[2 * j + 1];
            a0 = fma2(xp[4 * j + 0], ea.x, a0);
            a1 = fma2(xp[4 * j + 1], ea.y, a1);
            a2 = fma2(xp[4 * j + 2], eb.x, a2);
            a3 = fma2(xp[4 * j + 3], eb.y, a3);
        }
        u64v s2 = add2(add2(a0, a1), add2(a2, a3));
        float lo, hi;
        unpack2(s2, lo, hi);
        float dot = lo + hi;
        // 2*dot is exact (power-of-two scale), so FMA == fl((Sx+Se) - 2*dot).
        float dist = fmaf(-2.f, dot, Sx + se[k]);
        if (dist < best) { best = dist; bi = k; }
    }

    // Gather q = cb[bi], write q_st = lat + (q - lat), accumulate loss terms.
    float lsum = 0.f;
    const float4* qrow = (const float4*)(cb + (bi << 6));
#pragma unroll
    for (int j = 0; j < 16; j++) {
        float4 q = qrow[j];
        float x0, x1, x2v, x3v;
        unpack2(xp[2 * j + 0], x0, x1);
        unpack2(xp[2 * j + 1], x2v, x3v);
        float d0 = q.x - x0, d1 = q.y - x1, d2 = q.z - x2v, d3 = q.w - x3v;
        out[base + ((4 * j + 0) << 12)] = x0 + d0;
        out[base + ((4 * j + 1) << 12)] = x1 + d1;
        out[base + ((4 * j + 2) << 12)] = x2v + d2;
        out[base + ((4 * j + 3) << 12)] = x3v + d3;
        lsum = fmaf(d0, d0, lsum);
        lsum = fmaf(d1, d1, lsum);
        lsum = fmaf(d2, d2, lsum);
        lsum = fmaf(d3, d3, lsum);
    }

    // Deterministic block reduction of loss partial.
#pragma unroll
    for (int o = 16; o; o >>= 1) lsum += __shfl_xor_sync(0xffffffffu, lsum, o);
    if ((tid & 31) == 0) red[tid >> 5] = lsum;
    __syncthreads();
    if (tid == 0) {
        float t = 0.f;
#pragma unroll
        for (int w = 0; w < 8; w++) t += red[w];
        g_partials[blockIdx.x] = t;
    }
}

__global__ void vq_reduce(float* __restrict__ out) {
    __shared__ float s[NBLOCKS];
    const int t = threadIdx.x;
    s[t] = g_partials[t];
    __syncthreads();
#pragma unroll
    for (int o = 256; o; o >>= 1) {
        if (t < o) s[t] += s[t + o];
        __syncthreads();
    }
    if (t == 0) {
        float m = s[0] * (1.0f / 8388608.0f);   // mean (exact /2^23 up to one rounding)
        out[TENSOR_ELEMS] = 1.25f * m;          // beta*c + e == 1.25*mse
    }
}

extern "C" void kernel_launch(void* const* d_in, const int* in_sizes, int n_in,
                              void* d_out, int out_size) {
    const float* lat = (const float*)d_in[0];
    const float* emb = (const float*)d_in[1];
    float* out = (float*)d_out;

    const size_t smem_bytes = (size_t)(KC * DD + KC + 8) * sizeof(float); // ~133 KB
    cudaFuncSetAttribute(vq_kernel, cudaFuncAttributeMaxDynamicSharedMemorySize,
                         (int)smem_bytes);

    vq_kernel<<<NBLOCKS, 256, smem_bytes>>>(lat, emb, out);
    vq_reduce<<<1, NBLOCKS>>>(out);
}

// round 3
// speedup vs baseline: 1.3712x; 1.3712x over previous
#include <cuda_runtime.h>

// VectorQuantizer: latents [32,64,64,64] (B,D,H,W) fp32, emb_weight [512,64] fp32.
// Output: q_st transposed back to [B,D,H,W] (8388608 floats) + vq_loss (1 float).
//
// Frozen numerics contract (rel_err == 0.0 in R2):
//   Sx / Se: rounded squares, sequential sum.
//   dot: 4 independent FFMA2 chains, grouping a0:{4j},a1:{4j+1},a2:{4j+2},a3:{4j+3},
//        combined add2(add2(a0,a1),add2(a2,a3)), lo+hi.
//   dist = fmaf(-2, dot, Sx + Se[k]); strict '<' first-index argmin, k ascending.
//
// R3 change: 2 pixels/thread (halves LDS per FMA), explicit LDS.128 codebook loads.

#define DD        64
#define KC        512
#define HWPIX     4096
#define TENSOR_ELEMS 8388608
#define NBLOCKS   256           // 256 blocks * 256 threads * 2 px = 131072 pixels

typedef unsigned long long u64v;

__device__ __forceinline__ u64v fma2(u64v a, u64v b, u64v c) {
    u64v d_;
    asm("fma.rn.f32x2 %0, %1, %2, %3;" : "=l"(d_) : "l"(a), "l"(b), "l"(c));
    return d_;
}
__device__ __forceinline__ u64v add2(u64v a, u64v b) {
    u64v d_;
    asm("add.rn.f32x2 %0, %1, %2;" : "=l"(d_) : "l"(a), "l"(b));
    return d_;
}
__device__ __forceinline__ u64v pack2(float lo, float hi) {
    u64v d_;
    asm("mov.b64 %0, {%1, %2};" : "=l"(d_) : "f"(lo), "f"(hi));
    return d_;
}
__device__ __forceinline__ void unpack2(u64v v, float& lo, float& hi) {
    asm("mov.b64 {%0, %1}, %2;" : "=f"(lo), "=f"(hi) : "l"(v));
}
// Guaranteed LDS.128: two packed f32x2 values per load.
__device__ __forceinline__ void lds128(unsigned addr, u64v& e0, u64v& e1) {
    asm("ld.shared.v2.b64 {%0, %1}, [%2];" : "=l"(e0), "=l"(e1) : "r"(addr));
}

__device__ float g_partials[NBLOCKS];

__global__ void __launch_bounds__(256, 1)
vq_kernel(const float* __restrict__ lat, const float* __restrict__ emb,
          float* __restrict__ out) {
    extern __shared__ float smem[];
    float* cb  = smem;              // [512][64]
    float* se  = smem + KC * DD;    // [512]
    float* red = se + KC;           // [8]

    const int tid = threadIdx.x;

    // Stage codebook (coalesced float4).
    {
        float4* cb4 = (float4*)cb;
        const float4* e4 = (const float4*)emb;
#pragma unroll
        for (int i = 0; i < 32; i++) cb4[tid + 256 * i] = e4[tid + 256 * i];
    }
    __syncthreads();

    // Per-code squared norms (rounded squares, sequential sum).
    for (int k = tid; k < KC; k += 256) {
        const float* r = cb + k * DD;
        float s = 0.f;
#pragma unroll
        for (int d = 0; d < DD; d++) { float t = r[d] * r[d]; s = s + t; }
        se[k] = s;
    }
    __syncthreads();

    // Two pixels per thread: p0 and p0+256 (both coalesced per channel plane).
    const int p0    = blockIdx.x * 512 + tid;
    const int p1    = p0 + 256;
    const int base0 = ((p0 >> 12) << 18) + (p0 & (HWPIX - 1));
    const int base1 = ((p1 >> 12) << 18) + (p1 & (HWPIX - 1));

    u64v xp0[32], xp1[32];
    float Sx0 = 0.f, Sx1 = 0.f;
#pragma unroll
    for (int i = 0; i < 32; i++) {
        float a = lat[base0 + ((2 * i) << 12)];
        float c = lat[base0 + ((2 * i + 1) << 12)];
        float ta = a * a, tc = c * c;
        Sx0 = Sx0 + ta; Sx0 = Sx0 + tc;
        xp0[i] = pack2(a, c);
        float a2 = lat[base1 + ((2 * i) << 12)];
        float c2 = lat[base1 + ((2 * i + 1) << 12)];
        float ta2 = a2 * a2, tc2 = c2 * c2;
        Sx1 = Sx1 + ta2; Sx1 = Sx1 + tc2;
        xp1[i] = pack2(a2, c2);
    }

    const unsigned cbs = (unsigned)__cvta_generic_to_shared(cb);

    float best0 = 3.4e38f, best1 = 3.4e38f;
    int   bi0 = 0, bi1 = 0;
#pragma unroll 2
    for (int k = 0; k < KC; k++) {
        const unsigned row = cbs + ((unsigned)k << 8);   // 256 B per code row
        u64v a0 = 0ull, a1 = 0ull, a2 = 0ull, a3 = 0ull;
        u64v b0 = 0ull, b1 = 0ull, b2 = 0ull, b3 = 0ull;
#pragma unroll
        for (int j = 0; j < 8; j++) {
            u64v e0, e1, e2, e3;
            lds128(row + j * 32,      e0, e1);
            lds128(row + j * 32 + 16, e2, e3);
            a0 = fma2(xp0[4 * j + 0], e0, a0);
            a1 = fma2(xp0[4 * j + 1], e1, a1);
            a2 = fma2(xp0[4 * j + 2], e2, a2);
            a3 = fma2(xp0[4 * j + 3], e3, a3);
            b0 = fma2(xp1[4 * j + 0], e0, b0);
            b1 = fma2(xp1[4 * j + 1], e1, b1);
            b2 = fma2(xp1[4 * j + 2], e2, b2);
            b3 = fma2(xp1[4 * j + 3], e3, b3);
        }
        {
            u64v s2 = add2(add2(a0, a1), add2(a2, a3));
            float lo, hi; unpack2(s2, lo, hi);
            float dot = lo + hi;
            float dist = fmaf(-2.f, dot, Sx0 + se[k]);
            if (dist < best0) { best0 = dist; bi0 = k; }
        }
        {
            u64v s2 = add2(add2(b0, b1), add2(b2, b3));
            float lo, hi; unpack2(s2, lo, hi);
            float dot = lo + hi;
            float dist = fmaf(-2.f, dot, Sx1 + se[k]);
            if (dist < best1) { best1 = dist; bi1 = k; }
        }
    }

    // Epilogue: gather, straight-through write, loss partial.
    float lsum = 0.f;
    {
        const float4* qrow = (const float4*)(cb + (bi0 << 6));
#pragma unroll
        for (int j = 0; j < 16; j++) {
            float4 q = qrow[j];
            float x0, x1, x2v, x3v;
            unpack2(xp0[2 * j + 0], x0, x1);
            unpack2(xp0[2 * j + 1], x2v, x3v);
            float d0 = q.x - x0, d1 = q.y - x1, d2 = q.z - x2v, d3 = q.w - x3v;
            out[base0 + ((4 * j + 0) << 12)] = x0 + d0;
            out[base0 + ((4 * j + 1) << 12)] = x1 + d1;
            out[base0 + ((4 * j + 2) << 12)] = x2v + d2;
            out[base0 + ((4 * j + 3) << 12)] = x3v + d3;
            lsum = fmaf(d0, d0, lsum); lsum = fmaf(d1, d1, lsum);
            lsum = fmaf(d2, d2, lsum); lsum = fmaf(d3, d3, lsum);
        }
    }
    {
        const float4* qrow = (const float4*)(cb + (bi1 << 6));
#pragma unroll
        for (int j = 0; j < 16; j++) {
            float4 q = qrow[j];
            float x0, x1, x2v, x3v;
            unpack2(xp1[2 * j + 0], x0, x1);
            unpack2(xp1[2 * j + 1], x2v, x3v);
            float d0 = q.x - x0, d1 = q.y - x1, d2 = q.z - x2v, d3 = q.w - x3v;
            out[base1 + ((4 * j + 0) << 12)] = x0 + d0;
            out[base1 + ((4 * j + 1) << 12)] = x1 + d1;
            out[base1 + ((4 * j + 2) << 12)] = x2v + d2;
            out[base1 + ((4 * j + 3) << 12)] = x3v + d3;
            lsum = fmaf(d0, d0, lsum); lsum = fmaf(d1, d1, lsum);
            lsum = fmaf(d2, d2, lsum); lsum = fmaf(d3, d3, lsum);
        }
    }

#pragma unroll
    for (int o = 16; o; o >>= 1) lsum += __shfl_xor_sync(0xffffffffu, lsum, o);
    if ((tid & 31) == 0) red[tid >> 5] = lsum;
    __syncthreads();
    if (tid == 0) {
        float t = 0.f;
#pragma unroll
        for (int w = 0; w < 8; w++) t += red[w];
        g_partials[blockIdx.x] = t;
    }
}

__global__ void vq_reduce(float* __restrict__ out) {
    __shared__ float s[NBLOCKS];
    const int t = threadIdx.x;
    s[t] = g_partials[t];
    __syncthreads();
#pragma unroll
    for (int o = NBLOCKS / 2; o; o >>= 1) {
        if (t < o) s[t] += s[t + o];
        __syncthreads();
    }
    if (t == 0) {
        float m = s[0] * (1.0f / 8388608.0f);
        out[TENSOR_ELEMS] = 1.25f * m;
    }
}

extern "C" void kernel_launch(void* const* d_in, const int* in_sizes, int n_in,
                              void* d_out, int out_size) {
    const float* lat = (const float*)d_in[0];
    const float* emb = (const float*)d_in[1];
    float* out = (float*)d_out;

    const size_t smem_bytes = (size_t)(KC * DD + KC + 8) * sizeof(float); // ~133 KB
    cudaFuncSetAttribute(vq_kernel, cudaFuncAttributeMaxDynamicSharedMemorySize,
                         (int)smem_bytes);

    vq_kernel<<<NBLOCKS, 256, smem_bytes>>>(lat, emb, out);
    vq_reduce<<<1, NBLOCKS>>>(out);
}